// round 17
// baseline (speedup 1.0000x reference)
#include <cuda_runtime.h>
#include <cuda_bf16.h>
#include <math.h>

#define NB 4096
#define ND 128
#define LDA 40
#define LDP 132
#define MAXM 64
#define MARGINF 0.2f

__device__ __align__(16) float g_sq[NB];
__device__ __align__(16) float g_partial[NB];
__device__ __align__(16) float g_sim[(size_t)NB * NB];            // 64 MB
__device__ __align__(16) __nv_bfloat16 g_Xhi[(size_t)NB * ND];    // 1 MB
__device__ __align__(16) __nv_bfloat16 g_Xlo[(size_t)NB * ND];    // 1 MB

// ---------------- Kernel 1: norms + bf16 hi/lo split ----------------
__global__ void prep_kernel(const float* __restrict__ X) {
    int row = blockIdx.x * 8 + (threadIdx.x >> 5);
    int lane = threadIdx.x & 31;
    float4 v = ((const float4*)(X + (size_t)row * ND))[lane];
    float s = v.x * v.x + v.y * v.y + v.z * v.z + v.w * v.w;
    #pragma unroll
    for (int o = 16; o; o >>= 1) s += __shfl_xor_sync(0xffffffffu, s, o);
    if (lane == 0) g_sq[row] = s;
    __nv_bfloat16 h0 = __float2bfloat16(v.x), h1 = __float2bfloat16(v.y);
    __nv_bfloat16 h2 = __float2bfloat16(v.z), h3 = __float2bfloat16(v.w);
    __nv_bfloat16 l0 = __float2bfloat16(v.x - __bfloat162float(h0));
    __nv_bfloat16 l1 = __float2bfloat16(v.y - __bfloat162float(h1));
    __nv_bfloat16 l2 = __float2bfloat16(v.z - __bfloat162float(h2));
    __nv_bfloat16 l3 = __float2bfloat16(v.w - __bfloat162float(h3));
    size_t base = (size_t)row * ND + 4 * lane;
    ((__nv_bfloat162*)(g_Xhi + base))[0] = __nv_bfloat162(h0, h1);
    ((__nv_bfloat162*)(g_Xhi + base))[1] = __nv_bfloat162(h2, h3);
    ((__nv_bfloat162*)(g_Xlo + base))[0] = __nv_bfloat162(l0, l1);
    ((__nv_bfloat162*)(g_Xlo + base))[1] = __nv_bfloat162(l2, l3);
}

__device__ __forceinline__ float mksim(float si, float sj, float dot, bool mt) {
    float d2 = fmaxf(si + sj - 2.0f * dot, 0.0f);
    float s = (d2 == 0.0f) ? 0.0f : -sqrtf(d2);
    return mt ? s : s + MARGINF;
}

// ---------------- Kernel 2: mma.sync bf16 split-GEMM -> sim ----------------
// Symmetric 528 tiles. Mirror block now staged transposed in smem and stored
// fully coalesced (previously scattered STG.32). Dynamic smem unions the
// mainloop A/B double buffers (40,960 B) with the staging buffer (67,584 B).
__global__ __launch_bounds__(256, 2)
void gemm_mma_kernel(const int* __restrict__ labels) {
    int t = blockIdx.x;
    int bi = 0;
    while ((bi + 1) * (65 - (bi + 1)) / 2 <= t) bi++;
    int bj = bi + (t - bi * (65 - bi) / 2);

    extern __shared__ __align__(16) char dsm[];
    __nv_bfloat16* Asm = (__nv_bfloat16*)dsm;              // [2][128*LDA]
    __nv_bfloat16* Bsm = (__nv_bfloat16*)(dsm + 20480);    // [2][128*LDA]
    float* staging = (float*)dsm;                          // [128][LDP] (reuse)
    __shared__ float sqA[128], sqB[128];
    __shared__ int lbA[128], lbB[128];

    int tid = threadIdx.x, lane = tid & 31, wid = tid >> 5;
    int rowA = bi * 128, rowB = bj * 128;

    if (tid < 128) {
        sqA[tid] = g_sq[rowA + tid];
        lbA[tid] = labels[rowA + tid];
    } else {
        int tt = tid - 128;
        sqB[tt] = g_sq[rowB + tt];
        lbB[tt] = labels[rowB + tt];
    }

    int lrow = tid >> 1, lhalf = tid & 1;
    int wm = (wid & 3) * 32, wn = (wid >> 2) * 64;
    int ar = (lane & 7) + 8 * ((lane >> 3) & 1);
    int ac = 8 * (lane >> 4);
    int br = (lane & 7) + 8 * ((lane >> 4) & 1);
    int bc = 8 * ((lane >> 3) & 1);

    float d[2][8][4];
    #pragma unroll
    for (int mi = 0; mi < 2; mi++)
        #pragma unroll
        for (int nj = 0; nj < 8; nj++)
            #pragma unroll
            for (int q = 0; q < 4; q++) d[mi][nj][q] = 0.0f;

    uint4 arg0, arg1, brg0, brg1;
    {
        const uint4* As = (const uint4*)(g_Xhi + (size_t)(rowA + lrow) * ND + 16 * lhalf);
        const uint4* Bs = (const uint4*)(g_Xhi + (size_t)(rowB + lrow) * ND + 16 * lhalf);
        arg0 = As[0]; arg1 = As[1];
        brg0 = Bs[0]; brg1 = Bs[1];
    }
    ((uint4*)(Asm + lrow * LDA + 16 * lhalf))[0] = arg0;
    ((uint4*)(Asm + lrow * LDA + 16 * lhalf))[1] = arg1;
    ((uint4*)(Bsm + lrow * LDA + 16 * lhalf))[0] = brg0;
    ((uint4*)(Bsm + lrow * LDA + 16 * lhalf))[1] = brg1;
    __syncthreads();

    #pragma unroll
    for (int c = 0; c < 12; c++) {
        int cur = c & 1;
        if (c < 11) {
            int cn = c + 1;
            int seg = cn >> 2, k0 = (cn & 3) * 32;
            const __nv_bfloat16* Aps = (seg < 2) ? g_Xhi : g_Xlo;   // hi,hi,lo
            const __nv_bfloat16* Bps = (seg == 1) ? g_Xlo : g_Xhi;  // hi,lo,hi
            const uint4* As = (const uint4*)(Aps + (size_t)(rowA + lrow) * ND + k0 + 16 * lhalf);
            const uint4* Bs = (const uint4*)(Bps + (size_t)(rowB + lrow) * ND + k0 + 16 * lhalf);
            arg0 = As[0]; arg1 = As[1];
            brg0 = Bs[0]; brg1 = Bs[1];
        }
        unsigned sA = (unsigned)__cvta_generic_to_shared(Asm + cur * 128 * LDA);
        unsigned sB = (unsigned)__cvta_generic_to_shared(Bsm + cur * 128 * LDA);
        #pragma unroll
        for (int ks = 0; ks < 2; ks++) {
            unsigned a_[2][4], b_[8][2];
            #pragma unroll
            for (int mi = 0; mi < 2; mi++) {
                unsigned ad = sA + 2u * (unsigned)((wm + mi * 16 + ar) * LDA + ks * 16 + ac);
                asm volatile(
                    "ldmatrix.sync.aligned.m8n8.x4.shared.b16 {%0,%1,%2,%3}, [%4];"
                    : "=r"(a_[mi][0]), "=r"(a_[mi][1]), "=r"(a_[mi][2]), "=r"(a_[mi][3])
                    : "r"(ad));
            }
            #pragma unroll
            for (int np = 0; np < 4; np++) {
                unsigned bd = sB + 2u * (unsigned)((wn + np * 16 + br) * LDA + ks * 16 + bc);
                asm volatile(
                    "ldmatrix.sync.aligned.m8n8.x4.shared.b16 {%0,%1,%2,%3}, [%4];"
                    : "=r"(b_[2 * np][0]), "=r"(b_[2 * np][1]),
                      "=r"(b_[2 * np + 1][0]), "=r"(b_[2 * np + 1][1])
                    : "r"(bd));
            }
            #pragma unroll
            for (int mi = 0; mi < 2; mi++)
                #pragma unroll
                for (int nj = 0; nj < 8; nj++)
                    asm volatile(
                        "mma.sync.aligned.m16n8k16.row.col.f32.bf16.bf16.f32 "
                        "{%0,%1,%2,%3},{%4,%5,%6,%7},{%8,%9},{%0,%1,%2,%3};"
                        : "+f"(d[mi][nj][0]), "+f"(d[mi][nj][1]),
                          "+f"(d[mi][nj][2]), "+f"(d[mi][nj][3])
                        : "r"(a_[mi][0]), "r"(a_[mi][1]), "r"(a_[mi][2]), "r"(a_[mi][3]),
                          "r"(b_[nj][0]), "r"(b_[nj][1]));
        }
        if (c < 11) {
            int nxt = cur ^ 1;
            ((uint4*)(Asm + nxt * 128 * LDA + lrow * LDA + 16 * lhalf))[0] = arg0;
            ((uint4*)(Asm + nxt * 128 * LDA + lrow * LDA + 16 * lhalf))[1] = arg1;
            ((uint4*)(Bsm + nxt * 128 * LDA + lrow * LDA + 16 * lhalf))[0] = brg0;
            ((uint4*)(Bsm + nxt * 128 * LDA + lrow * LDA + 16 * lhalf))[1] = brg1;
        }
        __syncthreads();
    }
    // (final __syncthreads above: all warps done reading A/B -> staging reuse OK)

    // Epilogue: compute sim, direct coalesced-ish normal store, and (off-diag)
    // stage transposed into smem for a fully coalesced mirror store.
    int gid = lane >> 2, tig = lane & 3;
    #pragma unroll
    for (int mi = 0; mi < 2; mi++) {
        #pragma unroll
        for (int half = 0; half < 2; half++) {
            int ml = wm + mi * 16 + gid + 8 * half;
            float sa = sqA[ml];
            int la = lbA[ml];
            float* dst = g_sim + (size_t)(rowA + ml) * NB + rowB;
            #pragma unroll
            for (int nj = 0; nj < 8; nj++) {
                int nl = wn + nj * 8 + 2 * tig;
                float2 o;
                o.x = mksim(sa, sqB[nl],     d[mi][nj][2 * half],     la == lbB[nl]);
                o.y = mksim(sa, sqB[nl + 1], d[mi][nj][2 * half + 1], la == lbB[nl + 1]);
                *(float2*)(dst + nl) = o;
                if (bi != bj) {   // staging[nl][ml] = transposed tile
                    staging[nl * LDP + ml] = o.x;
                    staging[(nl + 1) * LDP + ml] = o.y;
                }
            }
        }
    }
    if (bi != bj) {
        __syncthreads();
        #pragma unroll
        for (int it = 0; it < 16; it++) {
            int idx = tid + 256 * it;
            int nl = idx >> 5, c4 = idx & 31;
            float4 v = *(float4*)(staging + nl * LDP + 4 * c4);
            *(float4*)(g_sim + (size_t)(rowB + nl) * NB + rowA + 4 * c4) = v;
        }
    }
}

// ---------------- Kernel 3: per-row rank-aware selection ----------------
__device__ __forceinline__ int gjf(int tid, int q) {
    return 4 * tid + 1024 * (q >> 2) + (q & 3);
}

__global__ __launch_bounds__(256, 4)
void phaseB_kernel(const int* __restrict__ labels) {
    __shared__ float vm[MAXM];
    __shared__ int jm[MAXM];
    __shared__ int cnt[MAXM];
    __shared__ float wv[8][MAXM];
    __shared__ int   wj[8][MAXM];
    __shared__ int mcount;

    const float NEG_INF = __int_as_float(0xff800000);
    const float POS_INF = __int_as_float(0x7f800000);
    const int   PMAX = 0x7fffffff;
    int tid = threadIdx.x, lane = tid & 31, wid = tid >> 5;
    int row = blockIdx.x;
    const float* simr = g_sim + (size_t)row * NB;
    int lr = labels[row];
    if (tid == 0) mcount = 0;
    __syncthreads();

    float ls[16];
    unsigned mrow = 0;
    #pragma unroll
    for (int t = 0; t < 4; t++) {
        int j4 = tid + 256 * t;
        float4 s4 = *(const float4*)(simr + 4 * (size_t)j4);
        int4 l4 = *(const int4*)(labels + 4 * j4);
        int b = 4 * t;
        ls[b + 0] = s4.x; ls[b + 1] = s4.y; ls[b + 2] = s4.z; ls[b + 3] = s4.w;
        if (l4.x == lr) mrow |= 1u << (b + 0);
        if (l4.y == lr) mrow |= 1u << (b + 1);
        if (l4.z == lr) mrow |= 1u << (b + 2);
        if (l4.w == lr) mrow |= 1u << (b + 3);
    }

    #pragma unroll
    for (int q = 0; q < 16; q++) {
        if ((mrow >> q) & 1u) {
            int p = atomicAdd(&mcount, 1);
            if (p < MAXM) { jm[p] = gjf(tid, q); vm[p] = ls[q]; cnt[p] = 0; }
        }
    }
    __syncthreads();
    int k = mcount;
    if (k > MAXM) k = MAXM;

    for (int m = 0; m < k; m++) {
        float vmv = vm[m];
        int jmi = jm[m];
        int c = 0;
        #pragma unroll
        for (int q = 0; q < 16; q++)
            c += (ls[q] > vmv || (ls[q] == vmv && gjf(tid, q) < jmi)) ? 1 : 0;
        c = __reduce_add_sync(0xffffffffu, c);
        if (lane == 0) atomicAdd(&cnt[m], c);
    }

    // Per-warp top-k via descending-threshold selection (register-resident).
    {
        float tv = POS_INF;
        int tp = -1;
        for (int e = 0; e < k; e++) {
            float bv = NEG_INF;
            int bp = PMAX;
            #pragma unroll
            for (int q = 0; q < 16; q++) {
                float v = ls[q];
                int p = (gjf(tid, q) << 1) | (int)((mrow >> q) & 1);
                bool after = (v < tv) || (v == tv && p > tp);
                bool better = (v > bv) || (v == bv && p < bp);
                if (after && better) { bv = v; bp = p; }
            }
            #pragma unroll
            for (int o = 16; o; o >>= 1) {
                float ov = __shfl_xor_sync(0xffffffffu, bv, o);
                int op = __shfl_xor_sync(0xffffffffu, bp, o);
                if (ov > bv || (ov == bv && op < bp)) { bv = ov; bp = op; }
            }
            if (lane == 0) { wv[wid][e] = bv; wj[wid][e] = bp; }
            tv = bv; tp = bp;
        }
    }
    __syncthreads();

    if (tid == 0) {
        int h[8] = {0, 0, 0, 0, 0, 0, 0, 0};
        float kf = (float)k;
        float fp_acc = 0.0f;
        for (int e = 1; e <= k; e++) {
            float bv = NEG_INF;
            int bp = PMAX, bw = 0;
            #pragma unroll
            for (int w = 0; w < 8; w++) {
                if (h[w] < k) {
                    float v = wv[w][h[w]];
                    int p = wj[w][h[w]];
                    if (v > bv || (v == bv && p < bp)) { bv = v; bp = p; bw = w; }
                }
            }
            h[bw]++;
            if (!(bp & 1))
                fp_acc += bv * (0.5f + (kf - (float)e + 1.0f) / kf * 0.5f);
        }
        float fn_acc = 0.0f;
        float nf = (float)NB;
        for (int m = 0; m < k; m++) {
            int rank = cnt[m] + 1;
            if (rank > k)
                fn_acc += vm[m] * (0.5f + ((float)rank - kf) / (nf - kf) * 0.5f);
        }
        g_partial[row] = fp_acc - fn_acc;
    }
}

__global__ void out_kernel(float* out) {
    __shared__ double red[256];
    int tid = threadIdx.x;
    double s = 0.0;
    #pragma unroll
    for (int t = 0; t < 16; t++) s += (double)g_partial[tid + 256 * t];
    red[tid] = s;
    __syncthreads();
    for (int o = 128; o; o >>= 1) {
        if (tid < o) red[tid] += red[tid + o];
        __syncthreads();
    }
    if (tid == 0) out[0] = (float)red[0];
}

extern "C" void kernel_launch(void* const* d_in, const int* in_sizes, int n_in,
                              void* d_out, int out_size) {
    const float* X = (const float*)d_in[0];
    const int* labels = (const int*)d_in[1];
    float* out = (float*)d_out;

    int dyn = 128 * LDP * 4;   // 67,584 B staging (>= 40,960 B mainloop A/B)
    cudaFuncSetAttribute(gemm_mma_kernel,
                         cudaFuncAttributeMaxDynamicSharedMemorySize, dyn);

    prep_kernel<<<NB / 8, 256>>>(X);
    gemm_mma_kernel<<<528, 256, dyn>>>(labels);
    phaseB_kernel<<<NB, 256>>>(labels);
    out_kernel<<<1, 256>>>(out);
}